// round 12
// baseline (speedup 1.0000x reference)
#include <cuda_runtime.h>
#include <cuda_bf16.h>
#include <math.h>

#define BZ   512
#define TM1  127

#define LDK   264                       // bf16 row stride for smem tiles
#define WTILE (128 * LDK * 2)           // 67584 B per W split tile
#define DTILE (32 * LDK * 2)            // 16896 B per d split tile
#define PRE_LD 34

typedef unsigned int uint32;

// ---------------- device state ----------------
__device__ float g_wenc[256];
__device__ __nv_bfloat16 g_dhi[2][512 * 256];   // [parity][batch][h]
__device__ __nv_bfloat16 g_dlo[2][512 * 256];
__device__ float g_ytilde[TM1][BZ];
__device__ float g_ctxfin[BZ];

// ---------------- kernel A: fused attention weight ----------------
__global__ void k_prep(const float* __restrict__ W_attn1,
                       const float* __restrict__ W_attn2) {
    int j = threadIdx.x;
    float acc = 0.f;
    #pragma unroll 4
    for (int k = 0; k < 128; ++k)
        acc += W_attn2[k] * W_attn1[k * 768 + 512 + j];
    g_wenc[j] = acc;
}

// ---------------- kernel B: scores -> softmax -> context -> folded dots ----------------
__global__ void k_attn(const float* __restrict__ X,
                       const float* __restrict__ y_prev,
                       const float* __restrict__ W_fc,
                       const float* __restrict__ b_fc,
                       const float* __restrict__ W_final) {
    __shared__ float wenc_s[256];
    __shared__ float sc[128];
    __shared__ float red[256];
    __shared__ float red2[256];
    const int b   = blockIdx.x;
    const int tid = threadIdx.x;
    const int lane = tid & 31, warp = tid >> 5;
    wenc_s[tid] = g_wenc[tid];
    __syncthreads();

    const float* Xb = X + (size_t)b * TM1 * 256;

    for (int t = warp; t < TM1; t += 8) {
        const float* xr = Xb + t * 256;
        float p = 0.f;
        #pragma unroll
        for (int i = 0; i < 8; ++i)
            p += xr[lane + 32 * i] * wenc_s[lane + 32 * i];
        #pragma unroll
        for (int o = 16; o; o >>= 1) p += __shfl_down_sync(0xffffffffu, p, o);
        if (lane == 0) sc[t] = p;
    }
    __syncthreads();

    float v = (tid < TM1) ? sc[tid] : -INFINITY;
    red[tid] = v; __syncthreads();
    for (int s = 128; s; s >>= 1) {
        if (tid < s) red[tid] = fmaxf(red[tid], red[tid + s]);
        __syncthreads();
    }
    float m = red[0];
    __syncthreads();
    float e = (tid < TM1) ? __expf(v - m) : 0.f;
    red[tid] = e; __syncthreads();
    for (int s = 128; s; s >>= 1) {
        if (tid < s) red[tid] += red[tid + s];
        __syncthreads();
    }
    float inv = 1.f / red[0];
    __syncthreads();
    if (tid < TM1) sc[tid] = e * inv;
    __syncthreads();

    float ctx = 0.f;
    #pragma unroll 4
    for (int t = 0; t < TM1; ++t)
        ctx += sc[t] * Xb[t * 256 + tid];

    red[tid]  = ctx * W_fc[tid];
    red2[tid] = ctx * W_final[256 + tid];
    __syncthreads();
    for (int s = 128; s; s >>= 1) {
        if (tid < s) { red[tid] += red[tid + s]; red2[tid] += red2[tid + s]; }
        __syncthreads();
    }
    float ytc = red[0] + b_fc[0];
    if (tid == 0) g_ctxfin[b] = red2[0];

    const float wfy = W_fc[256];
    for (int t = tid; t < TM1; t += 256)
        g_ytilde[t][b] = ytc + y_prev[b * TM1 + t] * wfy;
}

// ---------------- helpers ----------------
__device__ __forceinline__ float sigmoidf(float x) {
    return 1.f / (1.f + __expf(-x));
}
__device__ __forceinline__ float tanh_fast(float x) {
    return 2.f / (1.f + __expf(-2.f * x)) - 1.f;
}
__device__ __forceinline__ uint32 smem_u32(const void* p) {
    uint32 a;
    asm("{ .reg .u64 t; cvta.to.shared.u64 t, %1; cvt.u32.u64 %0, t; }" : "=r"(a) : "l"(p));
    return a;
}

#define LDSM4(r0, r1, r2, r3, addr) \
    asm volatile("ldmatrix.sync.aligned.m8n8.x4.shared.b16 {%0,%1,%2,%3}, [%4];" \
                 : "=r"(r0), "=r"(r1), "=r"(r2), "=r"(r3) : "r"(addr))

#define MMA16816(c, a, b0, b1) \
    asm volatile("mma.sync.aligned.m16n8k16.row.col.f32.bf16.bf16.f32 " \
                 "{%0,%1,%2,%3}, {%4,%5,%6,%7}, {%8,%9}, {%0,%1,%2,%3};" \
                 : "+f"(c[0]), "+f"(c[1]), "+f"(c[2]), "+f"(c[3]) \
                 : "r"(a[0]), "r"(a[1]), "r"(a[2]), "r"(a[3]), "r"(b0), "r"(b1))

// ---------------- persistent LSTM: mma.sync bf16 3-term, cluster mbarrier sync ----------------
// 128 CTAs = 16 clusters (batch groups) x 8 ranks (h-tiles).
// CTA tile: 128 gate rows (32 h, row r = h_local*4 + gate) x 32 batches, K = 256.
// smem byte offsets
#define OFF_WHI   0
#define OFF_WLO   (OFF_WHI + WTILE)             // 67584
#define OFF_DHI   (OFF_WLO + WTILE)             // 135168
#define OFF_DLO   (OFF_DHI + DTILE)             // 152064
#define OFF_PRE   (OFF_DLO + DTILE)             // 168960 (128*34*4 = 17408)
#define OFF_STHI  (OFF_PRE + 128 * PRE_LD * 4)  // 186368
#define OFF_STLO  (OFF_STHI + 2048)             // 188416
#define OFF_WIHB  (OFF_STLO + 2048)             // 190464
#define OFF_BIAS  (OFF_WIHB + 512)              // 190976
#define OFF_MBAR  (OFF_BIAS + 512)              // 191488
#define SMEM_LSTM (OFF_MBAR + 64)               // 191552

__global__ void __launch_bounds__(256, 1) __cluster_dims__(8, 1, 1)
k_lstm(const float* __restrict__ W_hh, const float* __restrict__ W_ih,
       const float* __restrict__ b_ih, const float* __restrict__ b_hh)
{
    extern __shared__ char smem[];
    __nv_bfloat16* Whi  = (__nv_bfloat16*)(smem + OFF_WHI);
    __nv_bfloat16* Wlo  = (__nv_bfloat16*)(smem + OFF_WLO);
    __nv_bfloat16* Dhi  = (__nv_bfloat16*)(smem + OFF_DHI);
    __nv_bfloat16* Dlo  = (__nv_bfloat16*)(smem + OFF_DLO);
    float*         pre  = (float*)(smem + OFF_PRE);
    __nv_bfloat16* sthi = (__nv_bfloat16*)(smem + OFF_STHI);
    __nv_bfloat16* stlo = (__nv_bfloat16*)(smem + OFF_STLO);
    float*         wihb = (float*)(smem + OFF_WIHB);
    float*         bias = (float*)(smem + OFF_BIAS);

    const int tid  = threadIdx.x;
    const int lane = tid & 31;
    const int warp = tid >> 5;
    const int bt    = blockIdx.x >> 3;     // batch group = cluster id (32 batches)
    const int gt    = blockIdx.x & 7;      // h tile = cluster rank (32 h)
    const int bbase = bt * 32;
    const uint32 sb = smem_u32(smem);
    const uint32 mbar = sb + OFF_MBAR;

    // ---- mbarrier init: 8 arrivals per phase (one from each cluster CTA) ----
    if (tid == 0) {
        asm volatile("mbarrier.init.shared.b64 [%0], %1;" :: "r"(mbar), "r"(8u) : "memory");
    }

    // ---- preload W tile split bf16 hi/lo; row r = h_local*4 + gate ----
    for (int idx = tid; idx < 128 * 64; idx += 256) {
        int r = idx >> 6, c4 = idx & 63;
        int gate = r & 3, h = gt * 32 + (r >> 2);
        float4 w = *(const float4*)(W_hh + (size_t)(gate * 256 + h) * 256 + c4 * 4);
        float wv[4] = {w.x, w.y, w.z, w.w};
        #pragma unroll
        for (int j = 0; j < 4; ++j) {
            __nv_bfloat16 hi = __float2bfloat16(wv[j]);
            __nv_bfloat16 lo = __float2bfloat16(wv[j] - __bfloat162float(hi));
            Whi[r * LDK + c4 * 4 + j] = hi;
            Wlo[r * LDK + c4 * 4 + j] = lo;
        }
    }
    if (tid < 128) {
        int gate = tid & 3, h = gt * 32 + (tid >> 2);
        int row = gate * 256 + h;
        wihb[tid] = W_ih[row];
        bias[tid] = b_ih[row] + b_hh[row];
    }

    // ---- zero my d slab in buf0: batches [bbase..+32), h [gt*32..+32) ----
    {
        uint4 z = make_uint4(0, 0, 0, 0);
        int i = tid & 127;
        int b = i >> 2, q = i & 3;
        size_t gi = (size_t)(bbase + b) * 32 + gt * 4 + q;   // uint4 units
        if (tid < 128) ((uint4*)g_dhi[0])[gi] = z;
        else           ((uint4*)g_dlo[0])[gi] = z;
    }

    // ---- MMA geometry: warp = m16 tile (8 warps = 128 rows), n = 32 batches ----
    const uint32 aHi = sb + OFF_WHI +
        (((warp * 16 + (lane & 15)) * LDK + ((lane >> 4) * 8)) * 2);
    const uint32 aLo = aHi + WTILE;

    const int bRow = ((lane >> 4) << 3) + (lane & 7);
    const int bCol = ((lane >> 3) & 1) * 8;
    const uint32 bHi0 = sb + OFF_DHI + ((bRow * LDK + bCol) * 2);
    const uint32 bHi1 = bHi0 + 16 * LDK * 2;
    const uint32 bLo0 = bHi0 + DTILE;
    const uint32 bLo1 = bHi1 + DTILE;

    // epilogue ownership: thread -> (b_local, 4 h values)
    const int b_local = tid & 31;
    const int hq = tid >> 5;               // == warp
    float c_reg[4] = {0.f, 0.f, 0.f, 0.f};

    // ---- one-time cluster sync: mbarrier inits + d zeros + W tiles visible ----
    __threadfence();
    __syncthreads();
    asm volatile("barrier.cluster.arrive.aligned;" ::: "memory");
    asm volatile("barrier.cluster.wait.aligned;" ::: "memory");

    uint32 ph = 0;   // mbarrier phase parity

    for (int t = 0; t < TM1; ++t) {
        const int p = t & 1;
        const __nv_bfloat16* gh = g_dhi[p];
        const __nv_bfloat16* gl = g_dlo[p];

        // ---- load d tile [32 b][256 h] hi+lo -> smem (coalesced uint4) ----
        #pragma unroll
        for (int i = 0; i < 2; ++i) {
            int idx = tid + i * 256;       // 0..511
            int b = idx >> 4, u = idx & 15;
            uint4 vh0 = __ldcg((const uint4*)gh + (size_t)(bbase + b) * 32 + u);
            uint4 vh1 = __ldcg((const uint4*)gh + (size_t)(bbase + b) * 32 + 16 + u);
            *(uint4*)((char*)Dhi + b * (LDK * 2) + u * 16) = vh0;
            *(uint4*)((char*)Dhi + b * (LDK * 2) + 256 + u * 16) = vh1;
            uint4 vl0 = __ldcg((const uint4*)gl + (size_t)(bbase + b) * 32 + u);
            uint4 vl1 = __ldcg((const uint4*)gl + (size_t)(bbase + b) * 32 + 16 + u);
            *(uint4*)((char*)Dlo + b * (LDK * 2) + u * 16) = vl0;
            *(uint4*)((char*)Dlo + b * (LDK * 2) + 256 + u * 16) = vl1;
        }
        float ytv = g_ytilde[t][bbase + b_local];
        __syncthreads();

        // ---- MMA: Whi*dhi + Whi*dlo + Wlo*dhi ----
        float acc[4][4];
        #pragma unroll
        for (int j = 0; j < 4; ++j)
            #pragma unroll
            for (int r = 0; r < 4; ++r) acc[j][r] = 0.f;

        #pragma unroll
        for (int ck = 0; ck < 16; ++ck) {
            const uint32 ko = ck * 32;
            uint32 ah[4], al[4], bh[8], bl[8];
            LDSM4(ah[0], ah[1], ah[2], ah[3], aHi + ko);
            LDSM4(al[0], al[1], al[2], al[3], aLo + ko);
            LDSM4(bh[0], bh[1], bh[2], bh[3], bHi0 + ko);
            LDSM4(bh[4], bh[5], bh[6], bh[7], bHi1 + ko);
            LDSM4(bl[0], bl[1], bl[2], bl[3], bLo0 + ko);
            LDSM4(bl[4], bl[5], bl[6], bl[7], bLo1 + ko);
            #pragma unroll
            for (int j = 0; j < 4; ++j) MMA16816(acc[j], ah, bh[2 * j], bh[2 * j + 1]);
            #pragma unroll
            for (int j = 0; j < 4; ++j) MMA16816(acc[j], ah, bl[2 * j], bl[2 * j + 1]);
            #pragma unroll
            for (int j = 0; j < 4; ++j) MMA16816(acc[j], al, bh[2 * j], bh[2 * j + 1]);
        }

        // ---- dump accumulators: pre[gate_row][b_local] ----
        {
            const int mrow = warp * 16 + (lane >> 2);
            const int ncol = (lane & 3) * 2;
            #pragma unroll
            for (int j = 0; j < 4; ++j) {
                *(float2*)&pre[mrow * PRE_LD + ncol + j * 8]       = make_float2(acc[j][0], acc[j][1]);
                *(float2*)&pre[(mrow + 8) * PRE_LD + ncol + j * 8] = make_float2(acc[j][2], acc[j][3]);
            }
        }
        __syncthreads();

        // ---- LSTM cell: thread owns (b_local, h = hq*4 .. +3) ----
        {
            __nv_bfloat16 dh4[4], dl4[4];
            #pragma unroll
            for (int hi_ = 0; hi_ < 4; ++hi_) {
                int hl = hq * 4 + hi_;
                float p0 = pre[(hl * 4 + 0) * PRE_LD + b_local] + ytv * wihb[hl * 4 + 0] + bias[hl * 4 + 0];
                float p1 = pre[(hl * 4 + 1) * PRE_LD + b_local] + ytv * wihb[hl * 4 + 1] + bias[hl * 4 + 1];
                float p2 = pre[(hl * 4 + 2) * PRE_LD + b_local] + ytv * wihb[hl * 4 + 2] + bias[hl * 4 + 2];
                float p3 = pre[(hl * 4 + 3) * PRE_LD + b_local] + ytv * wihb[hl * 4 + 3] + bias[hl * 4 + 3];
                float ig = sigmoidf(p0);
                float fg = sigmoidf(p1);
                float gg = tanh_fast(p2);
                float og = sigmoidf(p3);
                float cn = fg * c_reg[hi_] + ig * gg;
                c_reg[hi_] = cn;
                float d = og * tanh_fast(cn);
                __nv_bfloat16 dh = __float2bfloat16(d);
                dh4[hi_] = dh;
                dl4[hi_] = __float2bfloat16(d - __bfloat162float(dh));
            }
            *(uint2*)(sthi + b_local * 32 + hq * 4) = *(uint2*)dh4;
            *(uint2*)(stlo + b_local * 32 + hq * 4) = *(uint2*)dl4;
        }
        __syncthreads();

        // ---- coalesced slab store to buf p^1 ----
        {
            int i = tid & 127;
            int b = i >> 2, q = i & 3;
            size_t gi = (size_t)(bbase + b) * 32 + gt * 4 + q;
            if (tid < 128) ((uint4*)g_dhi[p ^ 1])[gi] = ((uint4*)sthi)[b * 4 + q];
            else           ((uint4*)g_dlo[p ^ 1])[gi] = ((uint4*)stlo)[b * 4 + q];
        }

        // ---- cluster mbarrier step barrier ----
        __syncthreads();                        // all slab stores issued block-wide
        if (tid < 8) {
            asm volatile("membar.gl;" ::: "memory");          // global stores -> L2 visible
            uint32 rem;
            asm("mapa.shared::cluster.u32 %0, %1, %2;" : "=r"(rem) : "r"(mbar), "r"(tid));
            asm volatile("mbarrier.arrive.release.cluster.shared::cluster.b64 _, [%0];"
                         :: "r"(rem) : "memory");
        }
        // every thread waits on the local barrier (8 arrivals), then proceeds
        asm volatile(
            "{\n\t.reg .pred P;\n"
            "W%=:\n\t"
            "mbarrier.try_wait.parity.acquire.cluster.shared::cta.b64 P, [%0], %1;\n\t"
            "@!P bra W%=;\n\t}"
            :: "r"(mbar), "r"(ph) : "memory");
        ph ^= 1;
    }

    // keep cluster alive until all CTAs pass the last barrier (no early exit races)
    asm volatile("barrier.cluster.arrive.aligned;" ::: "memory");
    asm volatile("barrier.cluster.wait.aligned;" ::: "memory");
}

// ---------------- final projection (last step wrote buf 1) ----------------
__global__ void k_final(const float* __restrict__ W_final,
                        const float* __restrict__ b_final,
                        float* __restrict__ out) {
    int b = blockIdx.x * 8 + (threadIdx.x >> 5);
    int lane = threadIdx.x & 31;
    float acc = 0.f;
    #pragma unroll
    for (int i = 0; i < 8; ++i) {
        int h = lane + 32 * i;
        size_t idx = (size_t)b * 256 + h;
        float d = __bfloat162float(g_dhi[1][idx]) + __bfloat162float(g_dlo[1][idx]);
        acc += d * W_final[h];
    }
    #pragma unroll
    for (int o = 16; o; o >>= 1) acc += __shfl_down_sync(0xffffffffu, acc, o);
    if (lane == 0) out[b] = acc + g_ctxfin[b] + b_final[0];
}

// ---------------- launch ----------------
extern "C" void kernel_launch(void* const* d_in, const int* in_sizes, int n_in,
                              void* d_out, int out_size) {
    const float* X       = (const float*)d_in[0];
    const float* y_prev  = (const float*)d_in[1];
    const float* W_attn1 = (const float*)d_in[2];
    const float* W_attn2 = (const float*)d_in[4];
    const float* W_fc    = (const float*)d_in[6];
    const float* b_fc    = (const float*)d_in[7];
    const float* W_ih    = (const float*)d_in[8];
    const float* W_hh    = (const float*)d_in[9];
    const float* b_ih    = (const float*)d_in[10];
    const float* b_hh    = (const float*)d_in[11];
    const float* W_final = (const float*)d_in[12];
    const float* b_final = (const float*)d_in[13];
    float* out = (float*)d_out;

    cudaFuncSetAttribute(k_lstm, cudaFuncAttributeMaxDynamicSharedMemorySize, SMEM_LSTM);

    k_prep<<<1, 256>>>(W_attn1, W_attn2);
    k_attn<<<BZ, 256>>>(X, y_prev, W_fc, b_fc, W_final);
    k_lstm<<<128, 256, SMEM_LSTM>>>(W_hh, W_ih, b_ih, b_hh);
    k_final<<<BZ / 8, 256>>>(W_final, b_final, out);
}

// round 14
// speedup vs baseline: 1.5476x; 1.5476x over previous
#include <cuda_runtime.h>
#include <cuda_bf16.h>
#include <math.h>

#define BZ   512
#define TM1  127

#define LDK   264                       // bf16 row stride for smem tiles
#define WTILE (128 * LDK * 2)           // 67584 B per W split tile
#define DTILE (32 * LDK * 2)            // 16896 B per d split tile
#define PRE_LD 34

typedef unsigned int uint32;

// ---------------- device state ----------------
__device__ float g_wenc[256];
__device__ __nv_bfloat16 g_dhi[2][512 * 256];   // [parity][batch][h]
__device__ __nv_bfloat16 g_dlo[2][512 * 256];
__device__ float g_ytilde[TM1][BZ];
__device__ float g_ctxfin[BZ];
__device__ unsigned g_cnt[16 * 32];             // per-batch-group barrier (128B stride)
__device__ unsigned g_gen[16 * 32];

// ---------------- kernel A: fused attention weight + barrier init ----------------
__global__ void k_prep(const float* __restrict__ W_attn1,
                       const float* __restrict__ W_attn2) {
    int j = threadIdx.x;
    float acc = 0.f;
    #pragma unroll 4
    for (int k = 0; k < 128; ++k)
        acc += W_attn2[k] * W_attn1[k * 768 + 512 + j];
    g_wenc[j] = acc;
    for (int i = j; i < 512; i += 256) { g_cnt[i] = 0; g_gen[i] = 0; }
}

// ---------------- kernel B: scores -> softmax -> context -> folded dots ----------------
__global__ void k_attn(const float* __restrict__ X,
                       const float* __restrict__ y_prev,
                       const float* __restrict__ W_fc,
                       const float* __restrict__ b_fc,
                       const float* __restrict__ W_final) {
    __shared__ float wenc_s[256];
    __shared__ float sc[128];
    __shared__ float red[256];
    __shared__ float red2[256];
    const int b   = blockIdx.x;
    const int tid = threadIdx.x;
    const int lane = tid & 31, warp = tid >> 5;
    wenc_s[tid] = g_wenc[tid];
    __syncthreads();

    const float* Xb = X + (size_t)b * TM1 * 256;

    for (int t = warp; t < TM1; t += 8) {
        const float* xr = Xb + t * 256;
        float p = 0.f;
        #pragma unroll
        for (int i = 0; i < 8; ++i)
            p += xr[lane + 32 * i] * wenc_s[lane + 32 * i];
        #pragma unroll
        for (int o = 16; o; o >>= 1) p += __shfl_down_sync(0xffffffffu, p, o);
        if (lane == 0) sc[t] = p;
    }
    __syncthreads();

    float v = (tid < TM1) ? sc[tid] : -INFINITY;
    red[tid] = v; __syncthreads();
    for (int s = 128; s; s >>= 1) {
        if (tid < s) red[tid] = fmaxf(red[tid], red[tid + s]);
        __syncthreads();
    }
    float m = red[0];
    __syncthreads();
    float e = (tid < TM1) ? __expf(v - m) : 0.f;
    red[tid] = e; __syncthreads();
    for (int s = 128; s; s >>= 1) {
        if (tid < s) red[tid] += red[tid + s];
        __syncthreads();
    }
    float inv = 1.f / red[0];
    __syncthreads();
    if (tid < TM1) sc[tid] = e * inv;
    __syncthreads();

    float ctx = 0.f;
    #pragma unroll 4
    for (int t = 0; t < TM1; ++t)
        ctx += sc[t] * Xb[t * 256 + tid];

    red[tid]  = ctx * W_fc[tid];
    red2[tid] = ctx * W_final[256 + tid];
    __syncthreads();
    for (int s = 128; s; s >>= 1) {
        if (tid < s) { red[tid] += red[tid + s]; red2[tid] += red2[tid + s]; }
        __syncthreads();
    }
    float ytc = red[0] + b_fc[0];
    if (tid == 0) g_ctxfin[b] = red2[0];

    const float wfy = W_fc[256];
    for (int t = tid; t < TM1; t += 256)
        g_ytilde[t][b] = ytc + y_prev[b * TM1 + t] * wfy;
}

// ---------------- helpers ----------------
__device__ __forceinline__ float sigmoidf(float x) {
    return 1.f / (1.f + __expf(-x));
}
__device__ __forceinline__ float tanh_fast(float x) {
    return 2.f / (1.f + __expf(-2.f * x)) - 1.f;
}
__device__ __forceinline__ uint32 smem_u32(const void* p) {
    uint32 a;
    asm("{ .reg .u64 t; cvta.to.shared.u64 t, %1; cvt.u32.u64 %0, t; }" : "=r"(a) : "l"(p));
    return a;
}

#define LDSM4(r0, r1, r2, r3, addr) \
    asm volatile("ldmatrix.sync.aligned.m8n8.x4.shared.b16 {%0,%1,%2,%3}, [%4];" \
                 : "=r"(r0), "=r"(r1), "=r"(r2), "=r"(r3) : "r"(addr))

#define MMA16816(c, a, b0, b1) \
    asm volatile("mma.sync.aligned.m16n8k16.row.col.f32.bf16.bf16.f32 " \
                 "{%0,%1,%2,%3}, {%4,%5,%6,%7}, {%8,%9}, {%0,%1,%2,%3};" \
                 : "+f"(c[0]), "+f"(c[1]), "+f"(c[2]), "+f"(c[3]) \
                 : "r"(a[0]), "r"(a[1]), "r"(a[2]), "r"(a[3]), "r"(b0), "r"(b1))

// ---------------- persistent LSTM: mma.sync bf16 3-term, Whi hoisted, scoped barriers ----------------
// 128 CTAs = 16 batch-groups x 8 h-tiles.
// CTA tile: 128 gate rows (32 h, row r = h_local*4 + gate) x 32 batches, K = 256.
// smem byte offsets
#define OFF_WHI   0
#define OFF_WLO   (OFF_WHI + WTILE)             // 67584
#define OFF_DHI   (OFF_WLO + WTILE)             // 135168
#define OFF_DLO   (OFF_DHI + DTILE)             // 152064
#define OFF_PRE   (OFF_DLO + DTILE)             // 168960 (128*34*4 = 17408)
#define OFF_STHI  (OFF_PRE + 128 * PRE_LD * 4)  // 186368
#define OFF_STLO  (OFF_STHI + 2048)             // 188416
#define OFF_WIHB  (OFF_STLO + 2048)             // 190464
#define OFF_BIAS  (OFF_WIHB + 512)              // 190976
#define SMEM_LSTM (OFF_BIAS + 512)              // 191488

__global__ void __launch_bounds__(256, 1)
k_lstm(const float* __restrict__ W_hh, const float* __restrict__ W_ih,
       const float* __restrict__ b_ih, const float* __restrict__ b_hh)
{
    extern __shared__ char smem[];
    __nv_bfloat16* Whi  = (__nv_bfloat16*)(smem + OFF_WHI);
    __nv_bfloat16* Wlo  = (__nv_bfloat16*)(smem + OFF_WLO);
    __nv_bfloat16* Dhi  = (__nv_bfloat16*)(smem + OFF_DHI);
    __nv_bfloat16* Dlo  = (__nv_bfloat16*)(smem + OFF_DLO);
    float*         pre  = (float*)(smem + OFF_PRE);
    __nv_bfloat16* sthi = (__nv_bfloat16*)(smem + OFF_STHI);
    __nv_bfloat16* stlo = (__nv_bfloat16*)(smem + OFF_STLO);
    float*         wihb = (float*)(smem + OFF_WIHB);
    float*         bias = (float*)(smem + OFF_BIAS);

    const int tid  = threadIdx.x;
    const int lane = tid & 31;
    const int warp = tid >> 5;
    const int bt    = blockIdx.x & 15;     // batch group: 32 batches
    const int gt    = blockIdx.x >> 4;     // h tile: 32 h = 128 gate rows
    const int bbase = bt * 32;

    // ---- preload W tile split bf16 hi/lo; row r = h_local*4 + gate ----
    for (int idx = tid; idx < 128 * 64; idx += 256) {
        int r = idx >> 6, c4 = idx & 63;
        int gate = r & 3, h = gt * 32 + (r >> 2);
        float4 w = *(const float4*)(W_hh + (size_t)(gate * 256 + h) * 256 + c4 * 4);
        float wv[4] = {w.x, w.y, w.z, w.w};
        #pragma unroll
        for (int j = 0; j < 4; ++j) {
            __nv_bfloat16 hi = __float2bfloat16(wv[j]);
            __nv_bfloat16 lo = __float2bfloat16(wv[j] - __bfloat162float(hi));
            Whi[r * LDK + c4 * 4 + j] = hi;
            Wlo[r * LDK + c4 * 4 + j] = lo;
        }
    }
    if (tid < 128) {
        int gate = tid & 3, h = gt * 32 + (tid >> 2);
        int row = gate * 256 + h;
        wihb[tid] = W_ih[row];
        bias[tid] = b_ih[row] + b_hh[row];
    }

    // ---- zero my d slab in buf0: batches [bbase..+32), h [gt*32..+32) ----
    {
        uint4 z = make_uint4(0, 0, 0, 0);
        int i = tid & 127;
        int b = i >> 2, q = i & 3;
        size_t gi = (size_t)(bbase + b) * 32 + gt * 4 + q;   // uint4 units
        if (tid < 128) ((uint4*)g_dhi[0])[gi] = z;
        else           ((uint4*)g_dlo[0])[gi] = z;
    }

    // ---- MMA geometry: warp = m16 tile (8 warps = 128 rows), n = 32 batches ----
    const uint32 sb = smem_u32(smem);
    const uint32 aHi = sb + OFF_WHI +
        (((warp * 16 + (lane & 15)) * LDK + ((lane >> 4) * 8)) * 2);
    const uint32 aLo = aHi + WTILE;

    const int bRow = ((lane >> 4) << 3) + (lane & 7);
    const int bCol = ((lane >> 3) & 1) * 8;
    const uint32 bHi0 = sb + OFF_DHI + ((bRow * LDK + bCol) * 2);
    const uint32 bHi1 = bHi0 + 16 * LDK * 2;
    const uint32 bLo0 = bHi0 + DTILE;
    const uint32 bLo1 = bHi1 + DTILE;

    __syncthreads();   // W smem tiles complete

    // ---- hoist loop-invariant Whi fragments into registers (64 regs) ----
    // Wlo stays in smem (hoisting both spilled in R9: 938us).
    uint32 ahr[16][4];
    #pragma unroll
    for (int ck = 0; ck < 16; ++ck)
        LDSM4(ahr[ck][0], ahr[ck][1], ahr[ck][2], ahr[ck][3], aHi + ck * 32);

    // epilogue ownership: thread -> (b_local, 4 h values)
    const int b_local = tid & 31;
    const int hq = tid >> 5;               // == warp
    float c_reg[4] = {0.f, 0.f, 0.f, 0.f};

    // group barrier bookkeeping (8 CTAs sharing batch group bt)
    unsigned* cnt = &g_cnt[bt * 32];
    unsigned* gen = &g_gen[bt * 32];

    // initial barrier: zeros visible group-wide
    __syncthreads();
    if (tid == 0) {
        unsigned g0 = *(volatile unsigned*)gen;
        __threadfence();
        if (atomicAdd(cnt, 1u) == 7u) { *cnt = 0u; __threadfence(); atomicExch(gen, g0 + 1u); }
        else { while (*(volatile unsigned*)gen == g0) {} }
        __threadfence();
    }
    __syncthreads();

    for (int t = 0; t < TM1; ++t) {
        const int p = t & 1;
        const __nv_bfloat16* gh = g_dhi[p];
        const __nv_bfloat16* gl = g_dlo[p];

        // ---- load d tile [32 b][256 h] hi+lo -> smem (coalesced uint4) ----
        #pragma unroll
        for (int i = 0; i < 2; ++i) {
            int idx = tid + i * 256;       // 0..511
            int b = idx >> 4, u = idx & 15;
            uint4 vh0 = __ldcg((const uint4*)gh + (size_t)(bbase + b) * 32 + u);
            uint4 vh1 = __ldcg((const uint4*)gh + (size_t)(bbase + b) * 32 + 16 + u);
            *(uint4*)((char*)Dhi + b * (LDK * 2) + u * 16) = vh0;
            *(uint4*)((char*)Dhi + b * (LDK * 2) + 256 + u * 16) = vh1;
            uint4 vl0 = __ldcg((const uint4*)gl + (size_t)(bbase + b) * 32 + u);
            uint4 vl1 = __ldcg((const uint4*)gl + (size_t)(bbase + b) * 32 + 16 + u);
            *(uint4*)((char*)Dlo + b * (LDK * 2) + u * 16) = vl0;
            *(uint4*)((char*)Dlo + b * (LDK * 2) + 256 + u * 16) = vl1;
        }
        float ytv = g_ytilde[t][bbase + b_local];
        __syncthreads();

        // ---- MMA: Whi*dhi + Whi*dlo + Wlo*dhi (Whi from registers) ----
        float acc[4][4];
        #pragma unroll
        for (int j = 0; j < 4; ++j)
            #pragma unroll
            for (int r = 0; r < 4; ++r) acc[j][r] = 0.f;

        #pragma unroll
        for (int ck = 0; ck < 16; ++ck) {
            const uint32 ko = ck * 32;
            uint32 al[4], bh[8], bl[8];
            LDSM4(bh[0], bh[1], bh[2], bh[3], bHi0 + ko);
            LDSM4(bh[4], bh[5], bh[6], bh[7], bHi1 + ko);
            LDSM4(bl[0], bl[1], bl[2], bl[3], bLo0 + ko);
            LDSM4(bl[4], bl[5], bl[6], bl[7], bLo1 + ko);
            LDSM4(al[0], al[1], al[2], al[3], aLo + ko);
            #pragma unroll
            for (int j = 0; j < 4; ++j) MMA16816(acc[j], ahr[ck], bh[2 * j], bh[2 * j + 1]);
            #pragma unroll
            for (int j = 0; j < 4; ++j) MMA16816(acc[j], ahr[ck], bl[2 * j], bl[2 * j + 1]);
            #pragma unroll
            for (int j = 0; j < 4; ++j) MMA16816(acc[j], al, bh[2 * j], bh[2 * j + 1]);
        }

        // ---- dump accumulators: pre[gate_row][b_local] ----
        {
            const int mrow = warp * 16 + (lane >> 2);
            const int ncol = (lane & 3) * 2;
            #pragma unroll
            for (int j = 0; j < 4; ++j) {
                *(float2*)&pre[mrow * PRE_LD + ncol + j * 8]       = make_float2(acc[j][0], acc[j][1]);
                *(float2*)&pre[(mrow + 8) * PRE_LD + ncol + j * 8] = make_float2(acc[j][2], acc[j][3]);
            }
        }
        __syncthreads();

        // ---- LSTM cell: thread owns (b_local, h = hq*4 .. +3) ----
        {
            __nv_bfloat16 dh4[4], dl4[4];
            #pragma unroll
            for (int hi_ = 0; hi_ < 4; ++hi_) {
                int hl = hq * 4 + hi_;
                float p0 = pre[(hl * 4 + 0) * PRE_LD + b_local] + ytv * wihb[hl * 4 + 0] + bias[hl * 4 + 0];
                float p1 = pre[(hl * 4 + 1) * PRE_LD + b_local] + ytv * wihb[hl * 4 + 1] + bias[hl * 4 + 1];
                float p2 = pre[(hl * 4 + 2) * PRE_LD + b_local] + ytv * wihb[hl * 4 + 2] + bias[hl * 4 + 2];
                float p3 = pre[(hl * 4 + 3) * PRE_LD + b_local] + ytv * wihb[hl * 4 + 3] + bias[hl * 4 + 3];
                float ig = sigmoidf(p0);
                float fg = sigmoidf(p1);
                float gg = tanh_fast(p2);
                float og = sigmoidf(p3);
                float cn = fg * c_reg[hi_] + ig * gg;
                c_reg[hi_] = cn;
                float d = og * tanh_fast(cn);
                __nv_bfloat16 dh = __float2bfloat16(d);
                dh4[hi_] = dh;
                dl4[hi_] = __float2bfloat16(d - __bfloat162float(dh));
            }
            *(uint2*)(sthi + b_local * 32 + hq * 4) = *(uint2*)dh4;
            *(uint2*)(stlo + b_local * 32 + hq * 4) = *(uint2*)dl4;
        }
        __syncthreads();

        // ---- coalesced slab store to buf p^1 ----
        {
            int i = tid & 127;
            int b = i >> 2, q = i & 3;
            size_t gi = (size_t)(bbase + b) * 32 + gt * 4 + q;
            if (tid < 128) ((uint4*)g_dhi[p ^ 1])[gi] = ((uint4*)sthi)[b * 4 + q];
            else           ((uint4*)g_dlo[p ^ 1])[gi] = ((uint4*)stlo)[b * 4 + q];
        }

        // ---- group barrier (8 CTAs sharing batch group) ----
        __syncthreads();
        if (tid == 0) {
            unsigned g0 = *(volatile unsigned*)gen;
            __threadfence();
            if (atomicAdd(cnt, 1u) == 7u) { *cnt = 0u; __threadfence(); atomicExch(gen, g0 + 1u); }
            else { while (*(volatile unsigned*)gen == g0) {} }
            __threadfence();
        }
        __syncthreads();
    }
}

// ---------------- final projection (last step wrote buf 1) ----------------
__global__ void k_final(const float* __restrict__ W_final,
                        const float* __restrict__ b_final,
                        float* __restrict__ out) {
    int b = blockIdx.x * 8 + (threadIdx.x >> 5);
    int lane = threadIdx.x & 31;
    float acc = 0.f;
    #pragma unroll
    for (int i = 0; i < 8; ++i) {
        int h = lane + 32 * i;
        size_t idx = (size_t)b * 256 + h;
        float d = __bfloat162float(g_dhi[1][idx]) + __bfloat162float(g_dlo[1][idx]);
        acc += d * W_final[h];
    }
    #pragma unroll
    for (int o = 16; o; o >>= 1) acc += __shfl_down_sync(0xffffffffu, acc, o);
    if (lane == 0) out[b] = acc + g_ctxfin[b] + b_final[0];
}

// ---------------- launch ----------------
extern "C" void kernel_launch(void* const* d_in, const int* in_sizes, int n_in,
                              void* d_out, int out_size) {
    const float* X       = (const float*)d_in[0];
    const float* y_prev  = (const float*)d_in[1];
    const float* W_attn1 = (const float*)d_in[2];
    const float* W_attn2 = (const float*)d_in[4];
    const float* W_fc    = (const float*)d_in[6];
    const float* b_fc    = (const float*)d_in[7];
    const float* W_ih    = (const float*)d_in[8];
    const float* W_hh    = (const float*)d_in[9];
    const float* b_ih    = (const float*)d_in[10];
    const float* b_hh    = (const float*)d_in[11];
    const float* W_final = (const float*)d_in[12];
    const float* b_final = (const float*)d_in[13];
    float* out = (float*)d_out;

    cudaFuncSetAttribute(k_lstm, cudaFuncAttributeMaxDynamicSharedMemorySize, SMEM_LSTM);

    k_prep<<<1, 256>>>(W_attn1, W_attn2);
    k_attn<<<BZ, 256>>>(X, y_prev, W_fc, b_fc, W_final);
    k_lstm<<<128, 256, SMEM_LSTM>>>(W_hh, W_ih, b_ih, b_hh);
    k_final<<<BZ / 8, 256>>>(W_final, b_final, out);
}

// round 15
// speedup vs baseline: 1.8007x; 1.1635x over previous
#include <cuda_runtime.h>
#include <cuda_fp16.h>
#include <math.h>

#define BZ   512
#define TM1  127

#define LDK   264                       // fp16 element row stride for smem tiles
#define WTILE (128 * LDK * 2)           // 67584 B per W split tile
#define DTILE (32 * LDK * 2)            // 16896 B d tile
#define PRE_LD 34

typedef unsigned int uint32;

// ---------------- device state ----------------
__device__ float g_wenc[256];
__device__ __half g_d[2][512 * 256];            // [parity][batch][h], fp16
__device__ float g_ytilde[TM1][BZ];
__device__ float g_ctxfin[BZ];
__device__ unsigned g_cnt[16 * 32];             // per-batch-group barrier (128B stride)
__device__ unsigned g_gen[16 * 32];

// ---------------- kernel A: fused attention weight + barrier init ----------------
__global__ void k_prep(const float* __restrict__ W_attn1,
                       const float* __restrict__ W_attn2) {
    int j = threadIdx.x;
    float acc = 0.f;
    #pragma unroll 4
    for (int k = 0; k < 128; ++k)
        acc += W_attn2[k] * W_attn1[k * 768 + 512 + j];
    g_wenc[j] = acc;
    for (int i = j; i < 512; i += 256) { g_cnt[i] = 0; g_gen[i] = 0; }
}

// ---------------- kernel B: scores -> softmax -> context -> folded dots ----------------
__global__ void k_attn(const float* __restrict__ X,
                       const float* __restrict__ y_prev,
                       const float* __restrict__ W_fc,
                       const float* __restrict__ b_fc,
                       const float* __restrict__ W_final) {
    __shared__ float wenc_s[256];
    __shared__ float sc[128];
    __shared__ float red[256];
    __shared__ float red2[256];
    const int b   = blockIdx.x;
    const int tid = threadIdx.x;
    const int lane = tid & 31, warp = tid >> 5;
    wenc_s[tid] = g_wenc[tid];
    __syncthreads();

    const float* Xb = X + (size_t)b * TM1 * 256;

    for (int t = warp; t < TM1; t += 8) {
        const float* xr = Xb + t * 256;
        float p = 0.f;
        #pragma unroll
        for (int i = 0; i < 8; ++i)
            p += xr[lane + 32 * i] * wenc_s[lane + 32 * i];
        #pragma unroll
        for (int o = 16; o; o >>= 1) p += __shfl_down_sync(0xffffffffu, p, o);
        if (lane == 0) sc[t] = p;
    }
    __syncthreads();

    float v = (tid < TM1) ? sc[tid] : -INFINITY;
    red[tid] = v; __syncthreads();
    for (int s = 128; s; s >>= 1) {
        if (tid < s) red[tid] = fmaxf(red[tid], red[tid + s]);
        __syncthreads();
    }
    float m = red[0];
    __syncthreads();
    float e = (tid < TM1) ? __expf(v - m) : 0.f;
    red[tid] = e; __syncthreads();
    for (int s = 128; s; s >>= 1) {
        if (tid < s) red[tid] += red[tid + s];
        __syncthreads();
    }
    float inv = 1.f / red[0];
    __syncthreads();
    if (tid < TM1) sc[tid] = e * inv;
    __syncthreads();

    float ctx = 0.f;
    #pragma unroll 4
    for (int t = 0; t < TM1; ++t)
        ctx += sc[t] * Xb[t * 256 + tid];

    red[tid]  = ctx * W_fc[tid];
    red2[tid] = ctx * W_final[256 + tid];
    __syncthreads();
    for (int s = 128; s; s >>= 1) {
        if (tid < s) { red[tid] += red[tid + s]; red2[tid] += red2[tid + s]; }
        __syncthreads();
    }
    float ytc = red[0] + b_fc[0];
    if (tid == 0) g_ctxfin[b] = red2[0];

    const float wfy = W_fc[256];
    for (int t = tid; t < TM1; t += 256)
        g_ytilde[t][b] = ytc + y_prev[b * TM1 + t] * wfy;
}

// ---------------- helpers ----------------
__device__ __forceinline__ float sigmoidf(float x) {
    return 1.f / (1.f + __expf(-x));
}
__device__ __forceinline__ float tanh_fast(float x) {
    return 2.f / (1.f + __expf(-2.f * x)) - 1.f;
}
__device__ __forceinline__ uint32 smem_u32(const void* p) {
    uint32 a;
    asm("{ .reg .u64 t; cvta.to.shared.u64 t, %1; cvt.u32.u64 %0, t; }" : "=r"(a) : "l"(p));
    return a;
}

#define LDSM4(r0, r1, r2, r3, addr) \
    asm volatile("ldmatrix.sync.aligned.m8n8.x4.shared.b16 {%0,%1,%2,%3}, [%4];" \
                 : "=r"(r0), "=r"(r1), "=r"(r2), "=r"(r3) : "r"(addr))

#define MMA16816F(c, a, b0, b1) \
    asm volatile("mma.sync.aligned.m16n8k16.row.col.f32.f16.f16.f32 " \
                 "{%0,%1,%2,%3}, {%4,%5,%6,%7}, {%8,%9}, {%0,%1,%2,%3};" \
                 : "+f"(c[0]), "+f"(c[1]), "+f"(c[2]), "+f"(c[3]) \
                 : "r"(a[0]), "r"(a[1]), "r"(a[2]), "r"(a[3]), "r"(b0), "r"(b1))

// ---------------- persistent LSTM: mma.sync fp16 2-term, scoped barriers ----------------
// 128 CTAs = 16 batch-groups x 8 h-tiles.
// CTA tile: 128 gate rows (32 h, row r = h_local*4 + gate) x 32 batches, K = 256.
// Numerics: W = Whi + Wlo (fp16 split, exact to 2^-22), d stored as single fp16.
// smem byte offsets
#define OFF_WHI   0
#define OFF_WLO   (OFF_WHI + WTILE)             // 67584
#define OFF_DHI   (OFF_WLO + WTILE)             // 135168
#define OFF_PRE   (OFF_DHI + DTILE)             // 152064 (128*34*4 = 17408)
#define OFF_ST    (OFF_PRE + 128 * PRE_LD * 4)  // 169472 (32b*32h*2B = 2048)
#define OFF_WIHB  (OFF_ST + 2048)               // 171520
#define OFF_BIAS  (OFF_WIHB + 512)              // 172032
#define SMEM_LSTM (OFF_BIAS + 512)              // 172544

__global__ void __launch_bounds__(256, 1)
k_lstm(const float* __restrict__ W_hh, const float* __restrict__ W_ih,
       const float* __restrict__ b_ih, const float* __restrict__ b_hh)
{
    extern __shared__ char smem[];
    __half* Whi = (__half*)(smem + OFF_WHI);
    __half* Wlo = (__half*)(smem + OFF_WLO);
    __half* Dhi = (__half*)(smem + OFF_DHI);
    float*  pre = (float*)(smem + OFF_PRE);
    __half* sth = (__half*)(smem + OFF_ST);
    float*  wihb = (float*)(smem + OFF_WIHB);
    float*  bias = (float*)(smem + OFF_BIAS);

    const int tid  = threadIdx.x;
    const int lane = tid & 31;
    const int warp = tid >> 5;
    const int bt    = blockIdx.x & 15;     // batch group: 32 batches
    const int gt    = blockIdx.x >> 4;     // h tile: 32 h = 128 gate rows
    const int bbase = bt * 32;

    // ---- preload W tile split fp16 hi/lo; row r = h_local*4 + gate ----
    for (int idx = tid; idx < 128 * 64; idx += 256) {
        int r = idx >> 6, c4 = idx & 63;
        int gate = r & 3, h = gt * 32 + (r >> 2);
        float4 w = *(const float4*)(W_hh + (size_t)(gate * 256 + h) * 256 + c4 * 4);
        float wv[4] = {w.x, w.y, w.z, w.w};
        #pragma unroll
        for (int j = 0; j < 4; ++j) {
            __half hi = __float2half_rn(wv[j]);
            __half lo = __float2half_rn(wv[j] - __half2float(hi));
            Whi[r * LDK + c4 * 4 + j] = hi;
            Wlo[r * LDK + c4 * 4 + j] = lo;
        }
    }
    if (tid < 128) {
        int gate = tid & 3, h = gt * 32 + (tid >> 2);
        int row = gate * 256 + h;
        wihb[tid] = W_ih[row];
        bias[tid] = b_ih[row] + b_hh[row];
    }

    // ---- zero my d slab in buf0: batches [bbase..+32), h [gt*32..+32) ----
    if (tid < 128) {
        uint4 z = make_uint4(0, 0, 0, 0);
        int b = tid >> 2, q = tid & 3;
        // row = 256 h fp16 = 512 B = 32 uint4; slab = 32 h = 4 uint4 per batch
        ((uint4*)g_d[0])[(size_t)(bbase + b) * 32 + gt * 4 + q] = z;
    }

    // ---- MMA geometry: warp = m16 tile (8 warps = 128 rows), n = 32 batches ----
    const uint32 sb = smem_u32(smem);
    const uint32 aHi = sb + OFF_WHI +
        (((warp * 16 + (lane & 15)) * LDK + ((lane >> 4) * 8)) * 2);
    const uint32 aLo = aHi + WTILE;

    const int bRow = ((lane >> 4) << 3) + (lane & 7);
    const int bCol = ((lane >> 3) & 1) * 8;
    const uint32 bHi0 = sb + OFF_DHI + ((bRow * LDK + bCol) * 2);
    const uint32 bHi1 = bHi0 + 16 * LDK * 2;

    __syncthreads();   // W smem tiles complete

    // ---- hoist loop-invariant Whi fragments into registers (64 regs) ----
    uint32 ahr[16][4];
    #pragma unroll
    for (int ck = 0; ck < 16; ++ck)
        LDSM4(ahr[ck][0], ahr[ck][1], ahr[ck][2], ahr[ck][3], aHi + ck * 32);

    // epilogue ownership: thread -> (b_local, 4 h values)
    const int b_local = tid & 31;
    const int hq = tid >> 5;               // == warp
    float c_reg[4] = {0.f, 0.f, 0.f, 0.f};

    // group barrier bookkeeping (8 CTAs sharing batch group bt)
    unsigned* cnt = &g_cnt[bt * 32];
    unsigned* gen = &g_gen[bt * 32];

    // initial barrier: zeros visible group-wide
    __syncthreads();
    if (tid == 0) {
        unsigned g0 = *(volatile unsigned*)gen;
        __threadfence();
        if (atomicAdd(cnt, 1u) == 7u) { *cnt = 0u; __threadfence(); atomicExch(gen, g0 + 1u); }
        else { while (*(volatile unsigned*)gen == g0) {} }
        __threadfence();
    }
    __syncthreads();

    for (int t = 0; t < TM1; ++t) {
        const int p = t & 1;
        const __half* gh = g_d[p];

        // ---- load d tile [32 b][256 h] fp16 -> smem (coalesced uint4) ----
        #pragma unroll
        for (int i = 0; i < 4; ++i) {
            int idx = tid + i * 256;       // 0..1023
            int b = idx >> 5, u = idx & 31;
            uint4 v = __ldcg((const uint4*)gh + (size_t)(bbase + b) * 32 + u);
            *(uint4*)((char*)Dhi + b * (LDK * 2) + u * 16) = v;
        }
        float ytv = g_ytilde[t][bbase + b_local];
        __syncthreads();

        // ---- MMA: Whi*d + Wlo*d (Whi from registers, Wlo from smem) ----
        float acc[4][4];
        #pragma unroll
        for (int j = 0; j < 4; ++j)
            #pragma unroll
            for (int r = 0; r < 4; ++r) acc[j][r] = 0.f;

        #pragma unroll
        for (int ck = 0; ck < 16; ++ck) {
            const uint32 ko = ck * 32;
            uint32 al[4], bh[8];
            LDSM4(bh[0], bh[1], bh[2], bh[3], bHi0 + ko);
            LDSM4(bh[4], bh[5], bh[6], bh[7], bHi1 + ko);
            LDSM4(al[0], al[1], al[2], al[3], aLo + ko);
            #pragma unroll
            for (int j = 0; j < 4; ++j) MMA16816F(acc[j], ahr[ck], bh[2 * j], bh[2 * j + 1]);
            #pragma unroll
            for (int j = 0; j < 4; ++j) MMA16816F(acc[j], al, bh[2 * j], bh[2 * j + 1]);
        }

        // ---- dump accumulators: pre[gate_row][b_local] ----
        {
            const int mrow = warp * 16 + (lane >> 2);
            const int ncol = (lane & 3) * 2;
            #pragma unroll
            for (int j = 0; j < 4; ++j) {
                *(float2*)&pre[mrow * PRE_LD + ncol + j * 8]       = make_float2(acc[j][0], acc[j][1]);
                *(float2*)&pre[(mrow + 8) * PRE_LD + ncol + j * 8] = make_float2(acc[j][2], acc[j][3]);
            }
        }
        __syncthreads();

        // ---- LSTM cell: thread owns (b_local, h = hq*4 .. +3) ----
        {
            __half dh4[4];
            #pragma unroll
            for (int hi_ = 0; hi_ < 4; ++hi_) {
                int hl = hq * 4 + hi_;
                float p0 = pre[(hl * 4 + 0) * PRE_LD + b_local] + ytv * wihb[hl * 4 + 0] + bias[hl * 4 + 0];
                float p1 = pre[(hl * 4 + 1) * PRE_LD + b_local] + ytv * wihb[hl * 4 + 1] + bias[hl * 4 + 1];
                float p2 = pre[(hl * 4 + 2) * PRE_LD + b_local] + ytv * wihb[hl * 4 + 2] + bias[hl * 4 + 2];
                float p3 = pre[(hl * 4 + 3) * PRE_LD + b_local] + ytv * wihb[hl * 4 + 3] + bias[hl * 4 + 3];
                float ig = sigmoidf(p0);
                float fg = sigmoidf(p1);
                float gg = tanh_fast(p2);
                float og = sigmoidf(p3);
                float cn = fg * c_reg[hi_] + ig * gg;
                c_reg[hi_] = cn;
                float d = og * tanh_fast(cn);
                dh4[hi_] = __float2half_rn(d);
            }
            *(uint2*)(sth + b_local * 32 + hq * 4) = *(uint2*)dh4;
        }
        __syncthreads();

        // ---- coalesced slab store to buf p^1 ----
        if (tid < 128) {
            int b = tid >> 2, q = tid & 3;
            ((uint4*)g_d[p ^ 1])[(size_t)(bbase + b) * 32 + gt * 4 + q] =
                ((uint4*)sth)[b * 4 + q];
        }

        // ---- group barrier (8 CTAs sharing batch group) ----
        __syncthreads();
        if (tid == 0) {
            unsigned g0 = *(volatile unsigned*)gen;
            __threadfence();
            if (atomicAdd(cnt, 1u) == 7u) { *cnt = 0u; __threadfence(); atomicExch(gen, g0 + 1u); }
            else { while (*(volatile unsigned*)gen == g0) {} }
            __threadfence();
        }
        __syncthreads();
    }
}

// ---------------- final projection (last step wrote buf 1) ----------------
__global__ void k_final(const float* __restrict__ W_final,
                        const float* __restrict__ b_final,
                        float* __restrict__ out) {
    int b = blockIdx.x * 8 + (threadIdx.x >> 5);
    int lane = threadIdx.x & 31;
    float acc = 0.f;
    #pragma unroll
    for (int i = 0; i < 8; ++i) {
        int h = lane + 32 * i;
        float d = __half2float(g_d[1][(size_t)b * 256 + h]);
        acc += d * W_final[h];
    }
    #pragma unroll
    for (int o = 16; o; o >>= 1) acc += __shfl_down_sync(0xffffffffu, acc, o);
    if (lane == 0) out[b] = acc + g_ctxfin[b] + b_final[0];
}

// ---------------- launch ----------------
extern "C" void kernel_launch(void* const* d_in, const int* in_sizes, int n_in,
                              void* d_out, int out_size) {
    const float* X       = (const float*)d_in[0];
    const float* y_prev  = (const float*)d_in[1];
    const float* W_attn1 = (const float*)d_in[2];
    const float* W_attn2 = (const float*)d_in[4];
    const float* W_fc    = (const float*)d_in[6];
    const float* b_fc    = (const float*)d_in[7];
    const float* W_ih    = (const float*)d_in[8];
    const float* W_hh    = (const float*)d_in[9];
    const float* b_ih    = (const float*)d_in[10];
    const float* b_hh    = (const float*)d_in[11];
    const float* W_final = (const float*)d_in[12];
    const float* b_final = (const float*)d_in[13];
    float* out = (float*)d_out;

    cudaFuncSetAttribute(k_lstm, cudaFuncAttributeMaxDynamicSharedMemorySize, SMEM_LSTM);

    k_prep<<<1, 256>>>(W_attn1, W_attn2);
    k_attn<<<BZ, 256>>>(X, y_prev, W_fc, b_fc, W_final);
    k_lstm<<<128, 256, SMEM_LSTM>>>(W_hh, W_ih, b_ih, b_hh);
    k_final<<<BZ / 8, 256>>>(W_final, b_final, out);
}

// round 17
// speedup vs baseline: 2.0090x; 1.1157x over previous
#include <cuda_runtime.h>
#include <cuda_fp16.h>
#include <math.h>

#define BZ   512
#define TM1  127

#define LDK   264                       // fp16 element row stride for smem tiles
#define WTILE (128 * LDK * 2)           // 67584 B W tile
#define DTILE (32 * LDK * 2)            // 16896 B d tile
#define PRE_LD 34

typedef unsigned int uint32;

// ---------------- device state ----------------
__device__ float g_wenc[256];
__device__ __half g_d[2][512 * 256];            // [parity][batch][h], fp16
__device__ float g_ytilde[TM1][BZ];
__device__ float g_ctxfin[BZ];
__device__ unsigned g_cnt[16 * 32];             // per-batch-group barrier (128B stride)
__device__ unsigned g_gen[16 * 32];

// ---------------- kernel A: fused attention weight + barrier init ----------------
__global__ void k_prep(const float* __restrict__ W_attn1,
                       const float* __restrict__ W_attn2) {
    int j = threadIdx.x;
    float acc = 0.f;
    #pragma unroll 4
    for (int k = 0; k < 128; ++k)
        acc += W_attn2[k] * W_attn1[k * 768 + 512 + j];
    g_wenc[j] = acc;
    for (int i = j; i < 512; i += 256) { g_cnt[i] = 0; g_gen[i] = 0; }
}

// ---------------- kernel B: scores -> softmax -> context -> folded dots ----------------
__global__ void k_attn(const float* __restrict__ X,
                       const float* __restrict__ y_prev,
                       const float* __restrict__ W_fc,
                       const float* __restrict__ b_fc,
                       const float* __restrict__ W_final) {
    __shared__ float wenc_s[256];
    __shared__ float sc[128];
    __shared__ float red[256];
    __shared__ float red2[256];
    const int b   = blockIdx.x;
    const int tid = threadIdx.x;
    const int lane = tid & 31, warp = tid >> 5;
    wenc_s[tid] = g_wenc[tid];
    __syncthreads();

    const float* Xb = X + (size_t)b * TM1 * 256;

    for (int t = warp; t < TM1; t += 8) {
        const float* xr = Xb + t * 256;
        float p = 0.f;
        #pragma unroll
        for (int i = 0; i < 8; ++i)
            p += xr[lane + 32 * i] * wenc_s[lane + 32 * i];
        #pragma unroll
        for (int o = 16; o; o >>= 1) p += __shfl_down_sync(0xffffffffu, p, o);
        if (lane == 0) sc[t] = p;
    }
    __syncthreads();

    float v = (tid < TM1) ? sc[tid] : -INFINITY;
    red[tid] = v; __syncthreads();
    for (int s = 128; s; s >>= 1) {
        if (tid < s) red[tid] = fmaxf(red[tid], red[tid + s]);
        __syncthreads();
    }
    float m = red[0];
    __syncthreads();
    float e = (tid < TM1) ? __expf(v - m) : 0.f;
    red[tid] = e; __syncthreads();
    for (int s = 128; s; s >>= 1) {
        if (tid < s) red[tid] += red[tid + s];
        __syncthreads();
    }
    float inv = 1.f / red[0];
    __syncthreads();
    if (tid < TM1) sc[tid] = e * inv;
    __syncthreads();

    float ctx = 0.f;
    #pragma unroll 4
    for (int t = 0; t < TM1; ++t)
        ctx += sc[t] * Xb[t * 256 + tid];

    red[tid]  = ctx * W_fc[tid];
    red2[tid] = ctx * W_final[256 + tid];
    __syncthreads();
    for (int s = 128; s; s >>= 1) {
        if (tid < s) { red[tid] += red[tid + s]; red2[tid] += red2[tid + s]; }
        __syncthreads();
    }
    float ytc = red[0] + b_fc[0];
    if (tid == 0) g_ctxfin[b] = red2[0];

    const float wfy = W_fc[256];
    for (int t = tid; t < TM1; t += 256)
        g_ytilde[t][b] = ytc + y_prev[b * TM1 + t] * wfy;
}

// ---------------- helpers ----------------
__device__ __forceinline__ float sigmoidf(float x) {
    return 1.f / (1.f + __expf(-x));
}
__device__ __forceinline__ float tanh_fast(float x) {
    return 2.f / (1.f + __expf(-2.f * x)) - 1.f;
}
__device__ __forceinline__ uint32 smem_u32(const void* p) {
    uint32 a;
    asm("{ .reg .u64 t; cvta.to.shared.u64 t, %1; cvt.u32.u64 %0, t; }" : "=r"(a) : "l"(p));
    return a;
}

#define LDSM4(r0, r1, r2, r3, addr) \
    asm volatile("ldmatrix.sync.aligned.m8n8.x4.shared.b16 {%0,%1,%2,%3}, [%4];" \
                 : "=r"(r0), "=r"(r1), "=r"(r2), "=r"(r3) : "r"(addr))

#define MMA16816F(c, a, b0, b1) \
    asm volatile("mma.sync.aligned.m16n8k16.row.col.f32.f16.f16.f32 " \
                 "{%0,%1,%2,%3}, {%4,%5,%6,%7}, {%8,%9}, {%0,%1,%2,%3};" \
                 : "+f"(c[0]), "+f"(c[1]), "+f"(c[2]), "+f"(c[3]) \
                 : "r"(a[0]), "r"(a[1]), "r"(a[2]), "r"(a[3]), "r"(b0), "r"(b1))

// ---------------- persistent LSTM: mma.sync fp16 1-term, scoped barriers ----------------
// 128 CTAs = 16 batch-groups x 8 h-tiles.
// CTA tile: 128 gate rows (32 h, row r = h_local*4 + gate) x 32 batches, K = 256.
// Numerics: W and d both single fp16 (validated by R14: fp16-d error -> 5.7e-6 output).
// smem byte offsets
#define OFF_WHI   0
#define OFF_DHI   (OFF_WHI + WTILE)             // 67584
#define OFF_PRE   (OFF_DHI + DTILE)             // 84480 (128*34*4 = 17408)
#define OFF_ST    (OFF_PRE + 128 * PRE_LD * 4)  // 101888 (2048)
#define OFF_WIHB  (OFF_ST + 2048)               // 103936
#define OFF_BIAS  (OFF_WIHB + 512)              // 104448
#define SMEM_LSTM (OFF_BIAS + 512)              // 104960

__global__ void __launch_bounds__(256, 1)
k_lstm(const float* __restrict__ W_hh, const float* __restrict__ W_ih,
       const float* __restrict__ b_ih, const float* __restrict__ b_hh)
{
    extern __shared__ char smem[];
    __half* Whi = (__half*)(smem + OFF_WHI);
    __half* Dhi = (__half*)(smem + OFF_DHI);
    float*  pre = (float*)(smem + OFF_PRE);
    __half* sth = (__half*)(smem + OFF_ST);
    float*  wihb = (float*)(smem + OFF_WIHB);
    float*  bias = (float*)(smem + OFF_BIAS);

    const int tid  = threadIdx.x;
    const int lane = tid & 31;
    const int warp = tid >> 5;
    const int bt    = blockIdx.x & 15;     // batch group: 32 batches
    const int gt    = blockIdx.x >> 4;     // h tile: 32 h = 128 gate rows
    const int bbase = bt * 32;

    // ---- preload W tile as single fp16; row r = h_local*4 + gate ----
    for (int idx = tid; idx < 128 * 64; idx += 256) {
        int r = idx >> 6, c4 = idx & 63;
        int gate = r & 3, h = gt * 32 + (r >> 2);
        float4 w = *(const float4*)(W_hh + (size_t)(gate * 256 + h) * 256 + c4 * 4);
        __half h4[4];
        h4[0] = __float2half_rn(w.x);
        h4[1] = __float2half_rn(w.y);
        h4[2] = __float2half_rn(w.z);
        h4[3] = __float2half_rn(w.w);
        *(uint2*)(Whi + r * LDK + c4 * 4) = *(uint2*)h4;
    }
    if (tid < 128) {
        int gate = tid & 3, h = gt * 32 + (tid >> 2);
        int row = gate * 256 + h;
        wihb[tid] = W_ih[row];
        bias[tid] = b_ih[row] + b_hh[row];
    }

    // ---- zero my d slab in buf0: batches [bbase..+32), h [gt*32..+32) ----
    if (tid < 128) {
        uint4 z = make_uint4(0, 0, 0, 0);
        int b = tid >> 2, q = tid & 3;
        ((uint4*)g_d[0])[(size_t)(bbase + b) * 32 + gt * 4 + q] = z;
    }

    // ---- MMA geometry: warp = m16 tile (8 warps = 128 rows), n = 32 batches ----
    const uint32 sb = smem_u32(smem);
    const uint32 aHi = sb + OFF_WHI +
        (((warp * 16 + (lane & 15)) * LDK + ((lane >> 4) * 8)) * 2);

    const int bRow = ((lane >> 4) << 3) + (lane & 7);
    const int bCol = ((lane >> 3) & 1) * 8;
    const uint32 bHi0 = sb + OFF_DHI + ((bRow * LDK + bCol) * 2);
    const uint32 bHi1 = bHi0 + 16 * LDK * 2;

    __syncthreads();   // W smem tile complete

    // ---- hoist all W fragments into registers (64 regs) ----
    uint32 ahr[16][4];
    #pragma unroll
    for (int ck = 0; ck < 16; ++ck)
        LDSM4(ahr[ck][0], ahr[ck][1], ahr[ck][2], ahr[ck][3], aHi + ck * 32);

    // epilogue ownership: thread -> (b_local, 4 h values)
    const int b_local = tid & 31;
    const int hq = tid >> 5;               // == warp
    float c_reg[4] = {0.f, 0.f, 0.f, 0.f};

    // group barrier bookkeeping (8 CTAs sharing batch group bt)
    unsigned* cnt = &g_cnt[bt * 32];
    unsigned* gen = &g_gen[bt * 32];

    // initial barrier: zeros visible group-wide
    __syncthreads();
    if (tid == 0) {
        unsigned g0 = *(volatile unsigned*)gen;
        __threadfence();
        if (atomicAdd(cnt, 1u) == 7u) { *cnt = 0u; __threadfence(); atomicExch(gen, g0 + 1u); }
        else { while (*(volatile unsigned*)gen == g0) {} }
        __threadfence();
    }
    __syncthreads();

    for (int t = 0; t < TM1; ++t) {
        const int p = t & 1;
        const __half* gh = g_d[p];

        // ---- load d tile [32 b][256 h] fp16 -> smem (coalesced uint4) ----
        #pragma unroll
        for (int i = 0; i < 4; ++i) {
            int idx = tid + i * 256;       // 0..1023
            int b = idx >> 5, u = idx & 31;
            uint4 v = __ldcg((const uint4*)gh + (size_t)(bbase + b) * 32 + u);
            *(uint4*)((char*)Dhi + b * (LDK * 2) + u * 16) = v;
        }
        float ytv = g_ytilde[t][bbase + b_local];
        __syncthreads();

        // ---- MMA: W*d, W fragments from registers ----
        float acc[4][4];
        #pragma unroll
        for (int j = 0; j < 4; ++j)
            #pragma unroll
            for (int r = 0; r < 4; ++r) acc[j][r] = 0.f;

        #pragma unroll
        for (int ck = 0; ck < 16; ++ck) {
            const uint32 ko = ck * 32;
            uint32 bh[8];
            LDSM4(bh[0], bh[1], bh[2], bh[3], bHi0 + ko);
            LDSM4(bh[4], bh[5], bh[6], bh[7], bHi1 + ko);
            #pragma unroll
            for (int j = 0; j < 4; ++j) MMA16816F(acc[j], ahr[ck], bh[2 * j], bh[2 * j + 1]);
        }

        // ---- dump accumulators: pre[gate_row][b_local] ----
        {
            const int mrow = warp * 16 + (lane >> 2);
            const int ncol = (lane & 3) * 2;
            #pragma unroll
            for (int j = 0; j < 4; ++j) {
                *(float2*)&pre[mrow * PRE_LD + ncol + j * 8]       = make_float2(acc[j][0], acc[j][1]);
                *(float2*)&pre[(mrow + 8) * PRE_LD + ncol + j * 8] = make_float2(acc[j][2], acc[j][3]);
            }
        }
        __syncthreads();

        // ---- LSTM cell: thread owns (b_local, h = hq*4 .. +3) ----
        {
            __half dh4[4];
            #pragma unroll
            for (int hi_ = 0; hi_ < 4; ++hi_) {
                int hl = hq * 4 + hi_;
                float p0 = pre[(hl * 4 + 0) * PRE_LD + b_local] + ytv * wihb[hl * 4 + 0] + bias[hl * 4 + 0];
                float p1 = pre[(hl * 4 + 1) * PRE_LD + b_local] + ytv * wihb[hl * 4 + 1] + bias[hl * 4 + 1];
                float p2 = pre[(hl * 4 + 2) * PRE_LD + b_local] + ytv * wihb[hl * 4 + 2] + bias[hl * 4 + 2];
                float p3 = pre[(hl * 4 + 3) * PRE_LD + b_local] + ytv * wihb[hl * 4 + 3] + bias[hl * 4 + 3];
                float ig = sigmoidf(p0);
                float fg = sigmoidf(p1);
                float gg = tanh_fast(p2);
                float og = sigmoidf(p3);
                float cn = fg * c_reg[hi_] + ig * gg;
                c_reg[hi_] = cn;
                float d = og * tanh_fast(cn);
                dh4[hi_] = __float2half_rn(d);
            }
            *(uint2*)(sth + b_local * 32 + hq * 4) = *(uint2*)dh4;
        }
        __syncthreads();

        // ---- coalesced slab store to buf p^1 ----
        if (tid < 128) {
            int b = tid >> 2, q = tid & 3;
            ((uint4*)g_d[p ^ 1])[(size_t)(bbase + b) * 32 + gt * 4 + q] =
                ((uint4*)sth)[b * 4 + q];
        }

        // ---- group barrier (8 CTAs sharing batch group) ----
        __syncthreads();
        if (tid == 0) {
            unsigned g0 = *(volatile unsigned*)gen;
            __threadfence();
            if (atomicAdd(cnt, 1u) == 7u) { *cnt = 0u; __threadfence(); atomicExch(gen, g0 + 1u); }
            else { while (*(volatile unsigned*)gen == g0) {} }
            __threadfence();
        }
        __syncthreads();
    }
}

// ---------------- final projection (last step wrote buf 1) ----------------
__global__ void k_final(const float* __restrict__ W_final,
                        const float* __restrict__ b_final,
                        float* __restrict__ out) {
    int b = blockIdx.x * 8 + (threadIdx.x >> 5);
    int lane = threadIdx.x & 31;
    float acc = 0.f;
    #pragma unroll
    for (int i = 0; i < 8; ++i) {
        int h = lane + 32 * i;
        float d = __half2float(g_d[1][(size_t)b * 256 + h]);
        acc += d * W_final[h];
    }
    #pragma unroll
    for (int o = 16; o; o >>= 1) acc += __shfl_down_sync(0xffffffffu, acc, o);
    if (lane == 0) out[b] = acc + g_ctxfin[b] + b_final[0];
}

// ---------------- launch ----------------
extern "C" void kernel_launch(void* const* d_in, const int* in_sizes, int n_in,
                              void* d_out, int out_size) {
    const float* X       = (const float*)d_in[0];
    const float* y_prev  = (const float*)d_in[1];
    const float* W_attn1 = (const float*)d_in[2];
    const float* W_attn2 = (const float*)d_in[4];
    const float* W_fc    = (const float*)d_in[6];
    const float* b_fc    = (const float*)d_in[7];
    const float* W_ih    = (const float*)d_in[8];
    const float* W_hh    = (const float*)d_in[9];
    const float* b_ih    = (const float*)d_in[10];
    const float* b_hh    = (const float*)d_in[11];
    const float* W_final = (const float*)d_in[12];
    const float* b_final = (const float*)d_in[13];
    float* out = (float*)d_out;

    cudaFuncSetAttribute(k_lstm, cudaFuncAttributeMaxDynamicSharedMemorySize, SMEM_LSTM);

    k_prep<<<1, 256>>>(W_attn1, W_attn2);
    k_attn<<<BZ, 256>>>(X, y_prev, W_fc, b_fc, W_final);
    k_lstm<<<128, 256, SMEM_LSTM>>>(W_hh, W_ih, b_ih, b_hh);
    k_final<<<BZ / 8, 256>>>(W_final, b_final, out);
}